// round 8
// baseline (speedup 1.0000x reference)
#include <cuda_runtime.h>
#include <cuda_bf16.h>
#include <cstdint>

#define BB   2
#define SS   2048
#define DD   1024
#define HH   16
#define KVHn 4
#define HD   64
#define WIN  64
#define MM   (BB*SS)   // 4096

typedef unsigned long long ull;

// packed f32x2 helpers (attention kernel)
#define PACK2(d, x, y)  asm("mov.b64 %0, {%1, %2};" : "=l"(d) : "f"(x), "f"(y))
#define DUP2(d, x)      asm("mov.b64 %0, {%1, %1};" : "=l"(d) : "f"(x))
#define UNPACK2(lo, hi, d) asm("mov.b64 {%0, %1}, %2;" : "=f"(lo), "=f"(hi) : "l"(d))
#define FMA2(d, a, b)   asm("fma.rn.f32x2 %0, %1, %2, %0;" : "+l"(d) : "l"(a), "l"(b))
#define MUL2(d, a, b)   asm("mul.rn.f32x2 %0, %1, %2;" : "=l"(d) : "l"(a), "l"(b))
#define ADD2(d, a, b)   asm("add.rn.f32x2 %0, %1, %2;" : "=l"(d) : "l"(a), "l"(b))

__device__ __forceinline__ uint32_t smem_u32(const void* p) {
    uint32_t a;
    asm("{ .reg .u64 t; cvta.to.shared.u64 t, %1; cvt.u32.u64 %0, t; }"
        : "=r"(a) : "l"(p));
    return a;
}

// warp-level tensor core + async copy (all plain sm_80+ ISA, no arch suffix)
__device__ __forceinline__ void ldsm4(uint32_t* r, uint32_t addr) {
    asm volatile("ldmatrix.sync.aligned.m8n8.x4.shared.b16 {%0,%1,%2,%3}, [%4];"
                 : "=r"(r[0]), "=r"(r[1]), "=r"(r[2]), "=r"(r[3]) : "r"(addr));
}
__device__ __forceinline__ void mma_bf16(float* c, const uint32_t* a, const uint32_t* b) {
    asm volatile(
        "mma.sync.aligned.m16n8k16.row.col.f32.bf16.bf16.f32 "
        "{%0,%1,%2,%3}, {%4,%5,%6,%7}, {%8,%9}, {%0,%1,%2,%3};"
        : "+f"(c[0]), "+f"(c[1]), "+f"(c[2]), "+f"(c[3])
        : "r"(a[0]), "r"(a[1]), "r"(a[2]), "r"(a[3]), "r"(b[0]), "r"(b[1]));
}
#define CPA16(dst, src) \
    asm volatile("cp.async.cg.shared.global [%0], [%1], 16;" :: "r"(dst), "l"(src) : "memory")
#define CPA_COMMIT() asm volatile("cp.async.commit_group;" ::: "memory")
#define CPA_WAIT0()  asm volatile("cp.async.wait_group 0;" ::: "memory")

// ---------------------------------------------------------------------------
// Device scratch
// ---------------------------------------------------------------------------
__device__ float g_q[MM * HH * HD];
__device__ float g_k[MM * KVHn * HD];
__device__ float g_v[MM * KVHn * HD];
__device__ __nv_bfloat16 g_xhi[MM * DD],  g_xlo[MM * DD];          // x split
__device__ __nv_bfloat16 g_wt_hi[1536 * DD], g_wt_lo[1536 * DD];   // [wq|wk|wv]^T
__device__ __nv_bfloat16 g_wo_hi[DD * DD],   g_wo_lo[DD * DD];     // wo^T
__device__ __nv_bfloat16 g_ahi[MM * DD],  g_alo[MM * DD];          // attn out split

// ---------------------------------------------------------------------------
// Split fp32 -> bf16 hi/lo (no transpose). 4 elems/thread.
// ---------------------------------------------------------------------------
__global__ __launch_bounds__(256) void split_kernel(
    const float* __restrict__ src, __nv_bfloat16* __restrict__ hi,
    __nv_bfloat16* __restrict__ lo)
{
    const int i = (blockIdx.x * 256 + threadIdx.x) * 4;
    float4 v = *(const float4*)&src[i];
    __nv_bfloat16 h0 = __float2bfloat16(v.x), h1 = __float2bfloat16(v.y);
    __nv_bfloat16 h2 = __float2bfloat16(v.z), h3 = __float2bfloat16(v.w);
    __nv_bfloat16 l0 = __float2bfloat16(v.x - __bfloat162float(h0));
    __nv_bfloat16 l1 = __float2bfloat16(v.y - __bfloat162float(h1));
    __nv_bfloat16 l2 = __float2bfloat16(v.z - __bfloat162float(h2));
    __nv_bfloat16 l3 = __float2bfloat16(v.w - __bfloat162float(h3));
    __nv_bfloat162 H[2] = {__halves2bfloat162(h0, h1), __halves2bfloat162(h2, h3)};
    __nv_bfloat162 L[2] = {__halves2bfloat162(l0, l1), __halves2bfloat162(l2, l3)};
    *(uint2*)&hi[i] = *(uint2*)H;
    *(uint2*)&lo[i] = *(uint2*)L;
}

// ---------------------------------------------------------------------------
// Transpose + split: W[1024][N] row-major -> T[rowOff+n][k] bf16 hi/lo (K=1024)
// ---------------------------------------------------------------------------
__global__ __launch_bounds__(256) void transpose_split_kernel(
    const float* __restrict__ W, int N,
    __nv_bfloat16* __restrict__ Thi, __nv_bfloat16* __restrict__ Tlo, int rowOff)
{
    __shared__ float tile[32][33];
    const int tx = threadIdx.x, ty = threadIdx.y;
    const int n0 = blockIdx.x * 32, k0 = blockIdx.y * 32;
    #pragma unroll
    for (int j = ty; j < 32; j += 8)
        tile[j][tx] = W[(k0 + j) * N + n0 + tx];
    __syncthreads();
    #pragma unroll
    for (int j = ty; j < 32; j += 8) {
        float v = tile[tx][j];
        __nv_bfloat16 h = __float2bfloat16(v);
        __nv_bfloat16 l = __float2bfloat16(v - __bfloat162float(h));
        Thi[(rowOff + n0 + j) * 1024 + k0 + tx] = h;
        Tlo[(rowOff + n0 + j) * 1024 + k0 + tx] = l;
    }
}

// ---------------------------------------------------------------------------
// HMMA GEMM v2: D[M,N] = A[M,1024] @ B[N,1024]^T, bf16 hi/lo 3-MMA split.
// 128x128x16 CTA tile, 128 threads, 4 warps x (64x64) warp tile.
// cp.async.cg double-buffered smem (2 stages x 24KB = 48KB static, the limit).
// Rows padded to 48B (3x16B, odd multiple of 16 mod 128 -> conflict-free
// ldmatrix). Split-major MMA order avoids same-accumulator RAW chains.
// mode 0: qkv epilogue (RoPE -> g_q/g_k/g_v); mode 1: plain fp32 -> outp.
// ---------------------------------------------------------------------------
__global__ __launch_bounds__(128) void mma_gemm_kernel(
    const __nv_bfloat16* __restrict__ Ahi, const __nv_bfloat16* __restrict__ Alo,
    const __nv_bfloat16* __restrict__ Bhi, const __nv_bfloat16* __restrict__ Blo,
    const float* __restrict__ fc, const float* __restrict__ fs,
    float* __restrict__ outp, int mode)
{
    // [stage][array: Ah, Al, Bh, Bl][128 rows * 24 elems] = 49152 B total
    __shared__ __align__(16) __nv_bfloat16 sm[2][4][128 * 24];

    const int tid  = threadIdx.x;
    const int lane = tid & 31, wid = tid >> 5;
    const int wm = wid & 1, wn = wid >> 1;       // warp grid 2m x 2n, 64x64 tile
    const int m0 = blockIdx.y * 128, n0 = blockIdx.x * 128;

    // gmem sources: one row per thread, 32B (2 x cp.async 16B) per array
    const int r = tid;
    const __nv_bfloat16* gsrc[4] = {
        &Ahi[(m0 + r) * 1024], &Alo[(m0 + r) * 1024],
        &Bhi[(n0 + r) * 1024], &Blo[(n0 + r) * 1024]
    };
    uint32_t sbase[2][4];
    #pragma unroll
    for (int st = 0; st < 2; st++)
        #pragma unroll
        for (int a = 0; a < 4; a++)
            sbase[st][a] = smem_u32(&sm[st][a][0]);
    const uint32_t sdst = r * 48;   // byte offset of this thread's row

    // ldmatrix base offsets (bytes)
    const uint32_t a_base = ((wm * 64 + (lane & 15)) * 24 + ((lane & 16) ? 8 : 0)) * 2;
    const uint32_t b_base = ((wn * 64 + (lane & 7) + ((lane & 16) ? 8 : 0)) * 24
                             + ((lane & 8) ? 8 : 0)) * 2;

    float acc[4][8][4];
    #pragma unroll
    for (int i = 0; i < 4; i++)
        #pragma unroll
        for (int j = 0; j < 8; j++)
            #pragma unroll
            for (int q = 0; q < 4; q++) acc[i][j][q] = 0.f;

    // prologue: stage 0
    #pragma unroll
    for (int a = 0; a < 4; a++) {
        CPA16(sbase[0][a] + sdst,      gsrc[a]);
        CPA16(sbase[0][a] + sdst + 16, gsrc[a] + 8);
    }
    CPA_COMMIT();

    for (int kc = 0; kc < 64; ++kc) {
        CPA_WAIT0();          // stage kc resident (all groups drained)
        __syncthreads();      // visible to all; prior reads of other buf done
        if (kc + 1 < 64) {
            const int st = (kc + 1) & 1;
            const int go = (kc + 1) * 16;
            #pragma unroll
            for (int a = 0; a < 4; a++) {
                CPA16(sbase[st][a] + sdst,      gsrc[a] + go);
                CPA16(sbase[st][a] + sdst + 16, gsrc[a] + go + 8);
            }
        }
        CPA_COMMIT();

        const int st = kc & 1;
        uint32_t Af[2][4][4], Bf[2][8][2];
        #pragma unroll
        for (int h = 0; h < 2; h++) {
            const uint32_t uA = sbase[st][h]     + a_base;
            const uint32_t uB = sbase[st][2 + h] + b_base;
            #pragma unroll
            for (int mt = 0; mt < 4; mt++) ldsm4(Af[h][mt], uA + mt * 768);
            #pragma unroll
            for (int np = 0; np < 4; np++) {
                uint32_t t[4];
                ldsm4(t, uB + np * 768);
                Bf[h][2 * np][0]     = t[0]; Bf[h][2 * np][1]     = t[1];
                Bf[h][2 * np + 1][0] = t[2]; Bf[h][2 * np + 1][1] = t[3];
            }
        }
        // split-major: consecutive MMAs hit different accumulators
        #pragma unroll
        for (int sp = 0; sp < 3; sp++) {
            const int ha = sp >> 1;   // 0,0,1 : hi*hi, hi*lo, lo*hi
            const int hb = sp & 1;
            #pragma unroll
            for (int mt = 0; mt < 4; mt++)
                #pragma unroll
                for (int nt = 0; nt < 8; nt++)
                    mma_bf16(acc[mt][nt], Af[ha][mt], Bf[hb][nt]);
        }
    }

    // ---- epilogue ----
    const int g = lane >> 2, t2 = (lane & 3) * 2;
    float* dst; int ld, coff; bool rope;
    if (mode == 1)      { dst = outp; ld = 1024; coff = n0;        rope = false; }
    else if (n0 < 1024) { dst = g_q;  ld = 1024; coff = n0;        rope = true;  }
    else if (n0 < 1280) { dst = g_k;  ld = 256;  coff = n0 - 1024; rope = true;  }
    else                { dst = g_v;  ld = 256;  coff = n0 - 1280; rope = false; }

    #pragma unroll
    for (int mt = 0; mt < 4; mt++) {
        #pragma unroll
        for (int h2 = 0; h2 < 2; h2++) {
            const int row = m0 + wm * 64 + mt * 16 + g + h2 * 8;
            const int s   = row & (SS - 1);
            #pragma unroll
            for (int nt = 0; nt < 8; nt++) {
                const int col = wn * 64 + nt * 8 + t2;   // 0..127 in block
                float v0 = acc[mt][nt][h2 * 2];
                float v1 = acc[mt][nt][h2 * 2 + 1];
                if (rope) {
                    const int j = ((n0 + col) & 63) >> 1;
                    float c  = fc[s * 32 + j];
                    float sn = fs[s * 32 + j];
                    float o0 = v0 * c  - v1 * sn;
                    float o1 = v0 * sn + v1 * c;
                    v0 = o0; v1 = o1;
                }
                *(float2*)&dst[row * ld + coff + col] = make_float2(v0, v1);
            }
        }
    }
}

// ---------------------------------------------------------------------------
// Sliding-window attention (f32x2 online softmax; emits bf16 hi/lo).
// ---------------------------------------------------------------------------
__global__ __launch_bounds__(128) void attn_kernel()
{
    __shared__ float Ks[80 * 68];
    __shared__ float Vs[80 * 68];
    const int b   = blockIdx.z;
    const int kvh = blockIdx.y;
    const int qbase  = blockIdx.x * 16;
    const int kstart = max(0, qbase - WIN);
    const int nrows  = qbase + 16 - kstart;    // <= 80
    const int tid = threadIdx.x;

    for (int i = tid; i < nrows * 16; i += 128) {
        int row = i >> 4, c = (i & 15) * 4;
        int gidx = ((b * SS + kstart + row) * KVHn + kvh) * 64 + c;
        *(float4*)&Ks[row * 68 + c] = *(const float4*)&g_k[gidx];
        *(float4*)&Vs[row * 68 + c] = *(const float4*)&g_v[gidx];
    }
    __syncthreads();

    const int half = tid & 1, pair = tid >> 1;
    const int rep = pair & 3, qi = pair >> 2;
    const int qg = qbase + qi;
    const int h  = kvh * 4 + rep;
    const unsigned pmask = 3u << ((tid & 31) & ~1);

    ull q2[16];
    {
        const float4* qp = (const float4*)&g_q[((b * SS + qg) * HH + h) * 64 + half * 32];
        #pragma unroll
        for (int t = 0; t < 8; t++) {
            float4 v = qp[t];
            PACK2(q2[2 * t],     v.x, v.y);
            PACK2(q2[2 * t + 1], v.z, v.w);
        }
    }

    ull acc2[16];
    #pragma unroll
    for (int d = 0; d < 16; d++) acc2[d] = 0ULL;
    float m = -1e30f, l = 0.f;

    const int j0 = max(0, qg - WIN) - kstart;
    const int j1 = qg - kstart;
    for (int j = j0; j <= j1; ++j) {
        const float4* kr = (const float4*)&Ks[j * 68 + half * 32];
        ull d2[4] = {0ULL, 0ULL, 0ULL, 0ULL};
        #pragma unroll
        for (int t = 0; t < 8; t++) {
            float4 kv = kr[t];
            ull k2a, k2b;
            PACK2(k2a, kv.x, kv.y);
            PACK2(k2b, kv.z, kv.w);
            FMA2(d2[(2 * t) & 3],     q2[2 * t],     k2a);
            FMA2(d2[(2 * t + 1) & 3], q2[2 * t + 1], k2b);
        }
        ull s01, s23, sall;
        ADD2(s01, d2[0], d2[1]);
        ADD2(s23, d2[2], d2[3]);
        ADD2(sall, s01, s23);
        float plo, phi;
        UNPACK2(plo, phi, sall);
        float partial = plo + phi;
        float sc = (partial + __shfl_xor_sync(pmask, partial, 1)) * 0.125f;

        if (sc > m) {
            float esc = __expf(m - sc);
            ull esc2; DUP2(esc2, esc);
            l *= esc;
            #pragma unroll
            for (int d = 0; d < 16; d++) { ull t2; MUL2(t2, acc2[d], esc2); acc2[d] = t2; }
            m = sc;
        }
        float p = __expf(sc - m);
        l += p;
        ull p2; DUP2(p2, p);
        const float4* vr = (const float4*)&Vs[j * 68 + half * 32];
        #pragma unroll
        for (int t = 0; t < 8; t++) {
            float4 vv = vr[t];
            ull v2a, v2b;
            PACK2(v2a, vv.x, vv.y);
            PACK2(v2b, vv.z, vv.w);
            FMA2(acc2[2 * t],     v2a, p2);
            FMA2(acc2[2 * t + 1], v2b, p2);
        }
    }

    const float inv = 1.f / l;
    const int obase = (b * SS + qg) * 1024 + h * 64 + half * 32;
    #pragma unroll
    for (int t = 0; t < 16; t++) {
        float x0, x1;
        UNPACK2(x0, x1, acc2[t]);
        x0 *= inv; x1 *= inv;
        __nv_bfloat16 h0 = __float2bfloat16(x0), h1 = __float2bfloat16(x1);
        __nv_bfloat16 l0 = __float2bfloat16(x0 - __bfloat162float(h0));
        __nv_bfloat16 l1 = __float2bfloat16(x1 - __bfloat162float(h1));
        __nv_bfloat162 H = __halves2bfloat162(h0, h1);
        __nv_bfloat162 L = __halves2bfloat162(l0, l1);
        *(uint32_t*)&g_ahi[obase + 2 * t] = *(uint32_t*)&H;
        *(uint32_t*)&g_alo[obase + 2 * t] = *(uint32_t*)&L;
    }
}

// ---------------------------------------------------------------------------
extern "C" void kernel_launch(void* const* d_in, const int* in_sizes, int n_in,
                              void* d_out, int out_size)
{
    const float* x  = (const float*)d_in[0];
    const float* fc = (const float*)d_in[1];
    const float* fs = (const float*)d_in[2];
    const float* wq = (const float*)d_in[3];
    const float* wk = (const float*)d_in[4];
    const float* wv = (const float*)d_in[5];
    const float* wo = (const float*)d_in[6];
    float* out = (float*)d_out;

    __nv_bfloat16 *xhi, *xlo, *wthi, *wtlo, *wohi, *wolo, *ahi, *alo;
    cudaGetSymbolAddress((void**)&xhi,  g_xhi);
    cudaGetSymbolAddress((void**)&xlo,  g_xlo);
    cudaGetSymbolAddress((void**)&wthi, g_wt_hi);
    cudaGetSymbolAddress((void**)&wtlo, g_wt_lo);
    cudaGetSymbolAddress((void**)&wohi, g_wo_hi);
    cudaGetSymbolAddress((void**)&wolo, g_wo_lo);
    cudaGetSymbolAddress((void**)&ahi,  g_ahi);
    cudaGetSymbolAddress((void**)&alo,  g_alo);

    // input conversions
    split_kernel<<<MM * DD / 1024, 256>>>(x, xhi, xlo);
    transpose_split_kernel<<<dim3(32, 32), dim3(32, 8)>>>(wq, 1024, wthi, wtlo, 0);
    transpose_split_kernel<<<dim3(8, 32),  dim3(32, 8)>>>(wk, 256,  wthi, wtlo, 1024);
    transpose_split_kernel<<<dim3(8, 32),  dim3(32, 8)>>>(wv, 256,  wthi, wtlo, 1280);
    transpose_split_kernel<<<dim3(32, 32), dim3(32, 8)>>>(wo, 1024, wohi, wolo, 0);

    // QKV projection + RoPE (HMMA, cp.async pipeline)
    mma_gemm_kernel<<<dim3(12, 32), 128>>>(xhi, xlo, wthi, wtlo, fc, fs, nullptr, 0);
    // attention
    attn_kernel<<<dim3(SS / 16, KVHn, BB), 128>>>();
    // output projection (HMMA, cp.async pipeline)
    mma_gemm_kernel<<<dim3(8, 32), 128>>>(ahi, alo, wohi, wolo, nullptr, nullptr, out, 1);
}